// round 3
// baseline (speedup 1.0000x reference)
#include <cuda_runtime.h>
#include <cstdint>

#define N_INS 8192
#define T_MAX 16
#define HID   256
#define GATES 1024
#define NCLUS 8

// ---------------- scratch (static device globals; no allocations) ----------
__device__ float g_H[2 * N_INS * HID];    // ping-pong hidden state
__device__ float g_C[N_INS * HID];        // cell state
__device__ float g_G[N_INS * GATES];      // precomputed ins_embeds @ Wih_i^T
__device__ float g_part[NCLUS * N_INS];   // per-cluster-CTA output partials

// ---------------- packed f32x2 helpers ----------
#define FMA2(d, a, b) \
    asm("fma.rn.f32x2 %0, %1, %2, %0;" : "+l"(d) : "l"(a), "l"(b))
#define UNPACK2(lo, hi, v) \
    asm("mov.b64 {%0, %1}, %2;" : "=f"(lo), "=f"(hi) : "l"(v))

__device__ __forceinline__ float fsig(float x) {
    return __fdividef(1.0f, 1.0f + __expf(-x));
}
__device__ __forceinline__ float ftanh_(float x) {
    float e2 = __expf(2.0f * fminf(x, 30.0f));
    return __fdividef(e2 - 1.0f, e2 + 1.0f);
}

__device__ __forceinline__ void fma8(unsigned long long* acc, float a,
                                     const ulonglong2& w01, const ulonglong2& w23) {
    unsigned long long ap;
    asm("mov.b64 %0, {%1, %1};" : "=l"(ap) : "r"(__float_as_uint(a)));
    FMA2(acc[0], ap, w01.x);
    FMA2(acc[1], ap, w01.y);
    FMA2(acc[2], ap, w23.x);
    FMA2(acc[3], ap, w23.y);
}

// ---------------------------------------------------------------------------
// f32x2 GEMM, 128x128 tile, 256 threads, 8x8 micro-tile (unchanged from R2,
// measured 216us, correct).
// ---------------------------------------------------------------------------
template<int MODE>
__global__ void __launch_bounds__(256)
gemm_k(float* __restrict__ Cmat,
       const float* __restrict__ A1, int lda1, const float* __restrict__ W1,
       const float* __restrict__ A2, const float* __restrict__ W2,
       const int* __restrict__ lengths,
       const float* __restrict__ bih, const float* __restrict__ bhh,
       const float* __restrict__ Hr, float* __restrict__ Hw,
       float* __restrict__ Cs, int t)
{
    __shared__ __align__(16) float As[16][132];
    __shared__ __align__(16) float Ws[16][132];

    const int tid = threadIdx.x;
    const int bm  = blockIdx.x * 128;
    const int bn  = blockIdx.y;
    const int tx  = tid & 15;
    const int ty  = tid >> 4;
    const int NT  = (MODE == 1) ? 32 : 16;

    const int lrow = tid >> 2;
    const int kq   = (tid & 3) << 2;

    int wr0, wr1;
    if (MODE == 1) {
        wr0 = (lrow & 3) * 256 + bn * 32 + (lrow >> 2);
        const int c1 = lrow + 64;
        wr1 = (c1 & 3) * 256 + bn * 32 + (c1 >> 2);
    } else {
        wr0 = bn * 128 + lrow;
        wr1 = bn * 128 + lrow + 64;
    }

    unsigned long long acc[8][4];
#pragma unroll
    for (int i = 0; i < 8; ++i)
#pragma unroll
        for (int j = 0; j < 4; ++j) acc[i][j] = 0ULL;

    float4 pa0, pa1, pw0, pw1;
    pa0 = *reinterpret_cast<const float4*>(A1 + (size_t)(bm + lrow)      * lda1 + kq);
    pa1 = *reinterpret_cast<const float4*>(A1 + (size_t)(bm + lrow + 64) * lda1 + kq);
    pw0 = *reinterpret_cast<const float4*>(W1 + (size_t)wr0 * 256 + kq);
    pw1 = *reinterpret_cast<const float4*>(W1 + (size_t)wr1 * 256 + kq);

    for (int tt = 0; tt < NT; ++tt) {
        __syncthreads();
        As[kq + 0][lrow] = pa0.x; As[kq + 1][lrow] = pa0.y;
        As[kq + 2][lrow] = pa0.z; As[kq + 3][lrow] = pa0.w;
        As[kq + 0][lrow + 64] = pa1.x; As[kq + 1][lrow + 64] = pa1.y;
        As[kq + 2][lrow + 64] = pa1.z; As[kq + 3][lrow + 64] = pa1.w;
        Ws[kq + 0][lrow] = pw0.x; Ws[kq + 1][lrow] = pw0.y;
        Ws[kq + 2][lrow] = pw0.z; Ws[kq + 3][lrow] = pw0.w;
        Ws[kq + 0][lrow + 64] = pw1.x; Ws[kq + 1][lrow + 64] = pw1.y;
        Ws[kq + 2][lrow + 64] = pw1.z; Ws[kq + 3][lrow + 64] = pw1.w;
        __syncthreads();

        if (tt + 1 < NT) {
            const int ts = tt + 1;
            const float* A; const float* W; int lda, k0;
            if (MODE == 1 && ts >= 16) { A = A2; lda = 256; W = W2; k0 = (ts - 16) * 16; }
            else                       { A = A1; lda = lda1; W = W1; k0 = ts * 16; }
            pa0 = *reinterpret_cast<const float4*>(A + (size_t)(bm + lrow)      * lda + k0 + kq);
            pa1 = *reinterpret_cast<const float4*>(A + (size_t)(bm + lrow + 64) * lda + k0 + kq);
            pw0 = *reinterpret_cast<const float4*>(W + (size_t)wr0 * 256 + k0 + kq);
            pw1 = *reinterpret_cast<const float4*>(W + (size_t)wr1 * 256 + k0 + kq);
        }

#pragma unroll
        for (int k = 0; k < 16; ++k) {
            const float4 a0 = *reinterpret_cast<const float4*>(&As[k][ty * 8]);
            const float4 a1 = *reinterpret_cast<const float4*>(&As[k][ty * 8 + 4]);
            const ulonglong2 w01 = *reinterpret_cast<const ulonglong2*>(&Ws[k][tx * 8]);
            const ulonglong2 w23 = *reinterpret_cast<const ulonglong2*>(&Ws[k][tx * 8 + 4]);
            fma8(acc[0], a0.x, w01, w23);
            fma8(acc[1], a0.y, w01, w23);
            fma8(acc[2], a0.z, w01, w23);
            fma8(acc[3], a0.w, w01, w23);
            fma8(acc[4], a1.x, w01, w23);
            fma8(acc[5], a1.y, w01, w23);
            fma8(acc[6], a1.z, w01, w23);
            fma8(acc[7], a1.w, w01, w23);
        }
    }

    if (MODE == 1) {
        const int ebase = bn * 32 + tx * 2;
        float b0[2], b1[2], b2[2], b3[2];
#pragma unroll
        for (int ee = 0; ee < 2; ++ee) {
            b0[ee] = bih[      ebase + ee] + bhh[      ebase + ee];
            b1[ee] = bih[256 + ebase + ee] + bhh[256 + ebase + ee];
            b2[ee] = bih[512 + ebase + ee] + bhh[512 + ebase + ee];
            b3[ee] = bih[768 + ebase + ee] + bhh[768 + ebase + ee];
        }
#pragma unroll
        for (int i = 0; i < 8; ++i) {
            const int m = bm + ty * 8 + i;
            const bool act = (t < lengths[m]);
#pragma unroll
            for (int ee = 0; ee < 2; ++ee) {
                const int off = m * 256 + ebase + ee;
                if (act) {
                    float gi, gf, gg, go;
                    UNPACK2(gi, gf, acc[i][ee * 2]);
                    UNPACK2(gg, go, acc[i][ee * 2 + 1]);
                    gi += b0[ee]; gf += b1[ee]; gg += b2[ee]; go += b3[ee];
                    float c = Cs[off];
                    c = fsig(gf) * c + fsig(gi) * ftanh_(gg);
                    Cs[off] = c;
                    Hw[off] = fsig(go) * ftanh_(c);
                } else {
                    Hw[off] = Hr[off];
                }
            }
        }
    } else {
#pragma unroll
        for (int i = 0; i < 8; ++i) {
            float o[8];
            UNPACK2(o[0], o[1], acc[i][0]);
            UNPACK2(o[2], o[3], acc[i][1]);
            UNPACK2(o[4], o[5], acc[i][2]);
            UNPACK2(o[6], o[7], acc[i][3]);
            float* dst = Cmat + (size_t)(bm + ty * 8 + i) * GATES + bn * 128 + tx * 8;
            *reinterpret_cast<float4*>(dst)     = make_float4(o[0], o[1], o[2], o[3]);
            *reinterpret_cast<float4*>(dst + 4) = make_float4(o[4], o[5], o[6], o[7]);
        }
    }
}

// ---------------------------------------------------------------------------
// Serial instruction LSTM: 8-CTA cluster, lock-free per-step flag sync.
// Producer warp0 lanes 0..7 each push the CTA's 32 new h values to ONE peer
// (8 x st.shared::cluster.v4) followed by a same-thread st.release of a
// monotonic step flag into that peer's flg[cta]. Consumers spin with cheap
// LOCAL ld.acquire polls (warp1 lanes 0..7, one flag each), then syncthreads.
// ---------------------------------------------------------------------------
__global__ void __launch_bounds__(512, 1) __cluster_dims__(NCLUS, 1, 1)
ins_lstm(const float* __restrict__ G,
         const float* __restrict__ Whh,
         const float* __restrict__ bih,
         const float* __restrict__ bhh,
         const float* __restrict__ Wl,
         float* __restrict__ part)
{
    __shared__ __align__(16) float hbuf[2][256];
    __shared__ float gs[128];
    __shared__ __align__(16) float hn[32];
    __shared__ __align__(16) unsigned int flg[8];

    const int tid = threadIdx.x;
    const int cta = blockIdx.x;
    const int r   = tid >> 2;
    const int q   = tid & 3;
    const int grow = (r >> 5) * 256 + cta * 32 + (r & 31);

    // pack this thread's 64 weights as 32 f32x2 pairs
    unsigned long long w2[32];
#pragma unroll
    for (int jj = 0; jj < 16; ++jj) {
        const float4 v = *reinterpret_cast<const float4*>(
            Whh + (size_t)grow * 256 + q * 64 + jj * 4);
        asm("mov.b64 %0, {%1, %2};" : "=l"(w2[2 * jj])
            : "r"(__float_as_uint(v.x)), "r"(__float_as_uint(v.y)));
        asm("mov.b64 %0, {%1, %2};" : "=l"(w2[2 * jj + 1])
            : "r"(__float_as_uint(v.z)), "r"(__float_as_uint(v.w)));
    }
    const float brow = bih[grow] + bhh[grow];
    const float wl = (tid < 32) ? Wl[cta * 32 + tid] : 0.0f;
    float cst = 0.0f;

    if (tid < 512) reinterpret_cast<float*>(hbuf)[tid] = 0.0f;
    if (tid < 8) flg[tid] = 0;

    const uint32_t hbase = (uint32_t)__cvta_generic_to_shared(&hbuf[0][0]);
    const uint32_t fbase = (uint32_t)__cvta_generic_to_shared(&flg[0]);

    // producer lanes: tid 0..7, peer = tid
    uint32_t rp_h = 0, rp_f = 0;
    if (tid < 8) {
        asm("mapa.shared::cluster.u32 %0, %1, %2;" : "=r"(rp_h) : "r"(hbase), "r"(tid));
        asm("mapa.shared::cluster.u32 %0, %1, %2;" : "=r"(rp_f) : "r"(fbase), "r"(tid));
        rp_f += (uint32_t)(cta * 4);
        rp_h += (uint32_t)(cta * 32 * 4);
    }

    __syncthreads();
    asm volatile("barrier.cluster.arrive.aligned;" ::: "memory");
    asm volatile("barrier.cluster.wait.aligned;" ::: "memory");

    float gp0 = 0.0f, gp1 = 0.0f;
    if (q == 0) {
        gp0 = __ldg(&G[grow]);
        gp1 = __ldg(&G[GATES + grow]);
    }

    int p = 0;
    for (int s = 0; s < N_INS; ++s) {
        // prefetch x-part of gates 2 steps ahead
        float gn = 0.0f;
        if (q == 0) {
            const int sn = (s + 2 < N_INS) ? s + 2 : N_INS - 1;
            gn = __ldg(&G[(size_t)sn * GATES + grow]);
        }

        // packed dot over this thread's 64-chunk of h
        const ulonglong2* hp = reinterpret_cast<const ulonglong2*>(&hbuf[p][q * 64]);
        unsigned long long a2 = 0ULL, b2 = 0ULL;
#pragma unroll
        for (int jj = 0; jj < 16; ++jj) {
            const ulonglong2 hv = hp[jj];
            FMA2(a2, w2[2 * jj],     hv.x);
            FMA2(b2, w2[2 * jj + 1], hv.y);
        }
        float s0, s1, s2, s3;
        UNPACK2(s0, s1, a2);
        UNPACK2(s2, s3, b2);
        float acc = (s0 + s1) + (s2 + s3);
        acc += __shfl_xor_sync(0xffffffffu, acc, 1);
        acc += __shfl_xor_sync(0xffffffffu, acc, 2);
        if (q == 0) gs[r] = acc + gp0 + brow;
        gp0 = gp1; gp1 = gn;
        __syncthreads();   // (A) gs complete + all reads of hbuf[p] done

        if (tid < 32) {
            const float gi = gs[tid];
            const float gf = gs[32 + tid];
            const float gg = gs[64 + tid];
            const float go = gs[96 + tid];
            cst = fsig(gf) * cst + fsig(gi) * ftanh_(gg);
            const float h = fsig(go) * ftanh_(cst);
            hn[tid] = h;
            __syncwarp();

            if (tid < 8) {
                // push all 32 h values to peer 'tid' hbuf[p^1][cta*32..]
                const float4* src = reinterpret_cast<const float4*>(hn);
                const uint32_t dst = rp_h + (uint32_t)((p ^ 1) * 256 * 4);
#pragma unroll
                for (int j = 0; j < 8; ++j) {
                    const float4 v = src[j];
                    asm volatile("st.shared::cluster.v4.f32 [%0], {%1, %2, %3, %4};"
                                 :: "r"(dst + j * 16),
                                    "f"(v.x), "f"(v.y), "f"(v.z), "f"(v.w) : "memory");
                }
                // same-thread release: orders the 8 stores above before the flag
                asm volatile("st.release.cluster.shared::cluster.u32 [%0], %1;"
                             :: "r"(rp_f), "r"(s + 1) : "memory");
            }

            // output projection (off critical path)
            float pp = h * wl;
#pragma unroll
            for (int o = 16; o > 0; o >>= 1)
                pp += __shfl_xor_sync(0xffffffffu, pp, o);
            if (tid == 0) part[(size_t)cta * N_INS + s] = pp;
        } else if (tid < 40) {
            // spin warp: wait for all 8 producers' flags (local SMEM polls)
            const uint32_t fa = fbase + (uint32_t)((tid - 32) * 4);
            uint32_t f;
            do {
                asm volatile("ld.acquire.cluster.shared::cta.u32 %0, [%1];"
                             : "=r"(f) : "r"(fa) : "memory");
            } while ((int)f < s + 1);
        }
        __syncthreads();   // (B) publish h(p^1) CTA-wide
        p ^= 1;
    }
}

// ---------------------------------------------------------------------------
__global__ void __launch_bounds__(256)
finalize(float* __restrict__ out, const float* __restrict__ part,
         const float* __restrict__ bl)
{
    const int n = blockIdx.x * 256 + threadIdx.x;
    float s = bl[0];
#pragma unroll
    for (int k = 0; k < NCLUS; ++k) s += part[(size_t)k * N_INS + n];
    out[n] = s;
}

// ---------------------------------------------------------------------------
extern "C" void kernel_launch(void* const* d_in, const int* in_sizes, int n_in,
                              void* d_out, int out_size)
{
    const float* tokens = (const float*)d_in[0];
    const int*   lengths= (const int*)  d_in[1];
    const float* Wih_t  = (const float*)d_in[2];
    const float* Whh_t  = (const float*)d_in[3];
    const float* bih_t  = (const float*)d_in[4];
    const float* bhh_t  = (const float*)d_in[5];
    const float* Wih_i  = (const float*)d_in[6];
    const float* Whh_i  = (const float*)d_in[7];
    const float* bih_i  = (const float*)d_in[8];
    const float* bhh_i  = (const float*)d_in[9];
    const float* Wl     = (const float*)d_in[10];
    const float* bl     = (const float*)d_in[11];
    float* out = (float*)d_out;

    float *H, *C, *G, *part;
    cudaGetSymbolAddress((void**)&H,    g_H);
    cudaGetSymbolAddress((void**)&C,    g_C);
    cudaGetSymbolAddress((void**)&G,    g_G);
    cudaGetSymbolAddress((void**)&part, g_part);

    cudaMemsetAsync(H, 0, (size_t)2 * N_INS * HID * sizeof(float));
    cudaMemsetAsync(C, 0, (size_t)N_INS * HID * sizeof(float));

    const size_t NH = (size_t)N_INS * HID;
    dim3 grid(N_INS / 128, 8);

    // ---- token-level LSTM: 16 fused GEMM+pointwise steps (H ping-pong) ----
    for (int t = 0; t < T_MAX; ++t) {
        float* hr = H + (size_t)(t & 1) * NH;
        float* hw = H + (size_t)((t & 1) ^ 1) * NH;
        gemm_k<1><<<grid, 256>>>(nullptr,
                                 tokens + (size_t)t * HID, T_MAX * HID, Wih_t,
                                 hr, Whh_t,
                                 lengths, bih_t, bhh_t,
                                 hr, hw, C, t);
    }

    // ---- precompute ins_embeds @ Wih_i^T into G ----
    gemm_k<0><<<grid, 256>>>(G, H, HID, Wih_i,
                             nullptr, nullptr, nullptr, nullptr, nullptr,
                             nullptr, nullptr, nullptr, 0);

    // ---- serial instruction-level LSTM (8-CTA cluster, flag sync) ----
    ins_lstm<<<NCLUS, 512>>>(G, Whh_i, bih_i, bhh_i, Wl, part);

    // ---- output projection finalize ----
    finalize<<<N_INS / 256, 256>>>(out, part, bl);
}

// round 4
// speedup vs baseline: 1.9606x; 1.9606x over previous
#include <cuda_runtime.h>
#include <cstdint>

#define N_INS 8192
#define T_MAX 16
#define HID   256
#define GATES 1024
#define NCLUS 8

// ---------------- scratch (static device globals; no allocations) ----------
__device__ float g_H[2 * N_INS * HID];    // ping-pong hidden state
__device__ float g_C[N_INS * HID];        // cell state
__device__ float g_G[N_INS * GATES];      // precomputed ins_embeds @ Wih_i^T
__device__ float g_part[NCLUS * N_INS];   // per-cluster-CTA output partials

// ---------------- packed f32x2 helpers ----------
#define FMA2(d, a, b) \
    asm("fma.rn.f32x2 %0, %1, %2, %0;" : "+l"(d) : "l"(a), "l"(b))
#define UNPACK2(lo, hi, v) \
    asm("mov.b64 {%0, %1}, %2;" : "=f"(lo), "=f"(hi) : "l"(v))

__device__ __forceinline__ float fsig(float x) {
    return __fdividef(1.0f, 1.0f + __expf(-x));
}
__device__ __forceinline__ float ftanh_(float x) {
    float e2 = __expf(2.0f * fminf(x, 30.0f));
    return __fdividef(e2 - 1.0f, e2 + 1.0f);
}

__device__ __forceinline__ void fma8(unsigned long long* acc, float a,
                                     const ulonglong2& w01, const ulonglong2& w23) {
    unsigned long long ap;
    asm("mov.b64 %0, {%1, %1};" : "=l"(ap) : "r"(__float_as_uint(a)));
    FMA2(acc[0], ap, w01.x);
    FMA2(acc[1], ap, w01.y);
    FMA2(acc[2], ap, w23.x);
    FMA2(acc[3], ap, w23.y);
}

// ---------------------------------------------------------------------------
// f32x2 GEMM, 128x128 tile, 256 threads, 8x8 micro-tile (measured 216us).
// MODE 1: dual-source + fused token-LSTM epilogue (gate-interleaved cols).
// MODE 0: single source, plain C = A1 @ W1^T.
// ---------------------------------------------------------------------------
template<int MODE>
__global__ void __launch_bounds__(256)
gemm_k(float* __restrict__ Cmat,
       const float* __restrict__ A1, int lda1, const float* __restrict__ W1,
       const float* __restrict__ A2, const float* __restrict__ W2,
       const int* __restrict__ lengths,
       const float* __restrict__ bih, const float* __restrict__ bhh,
       const float* __restrict__ Hr, float* __restrict__ Hw,
       float* __restrict__ Cs, int t)
{
    __shared__ __align__(16) float As[16][132];
    __shared__ __align__(16) float Ws[16][132];

    const int tid = threadIdx.x;
    const int bm  = blockIdx.x * 128;
    const int bn  = blockIdx.y;
    const int tx  = tid & 15;
    const int ty  = tid >> 4;
    const int NT  = (MODE == 1) ? 32 : 16;

    const int lrow = tid >> 2;
    const int kq   = (tid & 3) << 2;

    int wr0, wr1;
    if (MODE == 1) {
        wr0 = (lrow & 3) * 256 + bn * 32 + (lrow >> 2);
        const int c1 = lrow + 64;
        wr1 = (c1 & 3) * 256 + bn * 32 + (c1 >> 2);
    } else {
        wr0 = bn * 128 + lrow;
        wr1 = bn * 128 + lrow + 64;
    }

    unsigned long long acc[8][4];
#pragma unroll
    for (int i = 0; i < 8; ++i)
#pragma unroll
        for (int j = 0; j < 4; ++j) acc[i][j] = 0ULL;

    float4 pa0, pa1, pw0, pw1;
    pa0 = *reinterpret_cast<const float4*>(A1 + (size_t)(bm + lrow)      * lda1 + kq);
    pa1 = *reinterpret_cast<const float4*>(A1 + (size_t)(bm + lrow + 64) * lda1 + kq);
    pw0 = *reinterpret_cast<const float4*>(W1 + (size_t)wr0 * 256 + kq);
    pw1 = *reinterpret_cast<const float4*>(W1 + (size_t)wr1 * 256 + kq);

    for (int tt = 0; tt < NT; ++tt) {
        __syncthreads();
        As[kq + 0][lrow] = pa0.x; As[kq + 1][lrow] = pa0.y;
        As[kq + 2][lrow] = pa0.z; As[kq + 3][lrow] = pa0.w;
        As[kq + 0][lrow + 64] = pa1.x; As[kq + 1][lrow + 64] = pa1.y;
        As[kq + 2][lrow + 64] = pa1.z; As[kq + 3][lrow + 64] = pa1.w;
        Ws[kq + 0][lrow] = pw0.x; Ws[kq + 1][lrow] = pw0.y;
        Ws[kq + 2][lrow] = pw0.z; Ws[kq + 3][lrow] = pw0.w;
        Ws[kq + 0][lrow + 64] = pw1.x; Ws[kq + 1][lrow + 64] = pw1.y;
        Ws[kq + 2][lrow + 64] = pw1.z; Ws[kq + 3][lrow + 64] = pw1.w;
        __syncthreads();

        if (tt + 1 < NT) {
            const int ts = tt + 1;
            const float* A; const float* W; int lda, k0;
            if (MODE == 1 && ts >= 16) { A = A2; lda = 256; W = W2; k0 = (ts - 16) * 16; }
            else                       { A = A1; lda = lda1; W = W1; k0 = ts * 16; }
            pa0 = *reinterpret_cast<const float4*>(A + (size_t)(bm + lrow)      * lda + k0 + kq);
            pa1 = *reinterpret_cast<const float4*>(A + (size_t)(bm + lrow + 64) * lda + k0 + kq);
            pw0 = *reinterpret_cast<const float4*>(W + (size_t)wr0 * 256 + k0 + kq);
            pw1 = *reinterpret_cast<const float4*>(W + (size_t)wr1 * 256 + k0 + kq);
        }

#pragma unroll
        for (int k = 0; k < 16; ++k) {
            const float4 a0 = *reinterpret_cast<const float4*>(&As[k][ty * 8]);
            const float4 a1 = *reinterpret_cast<const float4*>(&As[k][ty * 8 + 4]);
            const ulonglong2 w01 = *reinterpret_cast<const ulonglong2*>(&Ws[k][tx * 8]);
            const ulonglong2 w23 = *reinterpret_cast<const ulonglong2*>(&Ws[k][tx * 8 + 4]);
            fma8(acc[0], a0.x, w01, w23);
            fma8(acc[1], a0.y, w01, w23);
            fma8(acc[2], a0.z, w01, w23);
            fma8(acc[3], a0.w, w01, w23);
            fma8(acc[4], a1.x, w01, w23);
            fma8(acc[5], a1.y, w01, w23);
            fma8(acc[6], a1.z, w01, w23);
            fma8(acc[7], a1.w, w01, w23);
        }
    }

    if (MODE == 1) {
        const int ebase = bn * 32 + tx * 2;
        float b0[2], b1[2], b2[2], b3[2];
#pragma unroll
        for (int ee = 0; ee < 2; ++ee) {
            b0[ee] = bih[      ebase + ee] + bhh[      ebase + ee];
            b1[ee] = bih[256 + ebase + ee] + bhh[256 + ebase + ee];
            b2[ee] = bih[512 + ebase + ee] + bhh[512 + ebase + ee];
            b3[ee] = bih[768 + ebase + ee] + bhh[768 + ebase + ee];
        }
#pragma unroll
        for (int i = 0; i < 8; ++i) {
            const int m = bm + ty * 8 + i;
            const bool act = (t < lengths[m]);
#pragma unroll
            for (int ee = 0; ee < 2; ++ee) {
                const int off = m * 256 + ebase + ee;
                if (act) {
                    float gi, gf, gg, go;
                    UNPACK2(gi, gf, acc[i][ee * 2]);
                    UNPACK2(gg, go, acc[i][ee * 2 + 1]);
                    gi += b0[ee]; gf += b1[ee]; gg += b2[ee]; go += b3[ee];
                    float c = Cs[off];
                    c = fsig(gf) * c + fsig(gi) * ftanh_(gg);
                    Cs[off] = c;
                    Hw[off] = fsig(go) * ftanh_(c);
                } else {
                    Hw[off] = Hr[off];
                }
            }
        }
    } else {
#pragma unroll
        for (int i = 0; i < 8; ++i) {
            float o[8];
            UNPACK2(o[0], o[1], acc[i][0]);
            UNPACK2(o[2], o[3], acc[i][1]);
            UNPACK2(o[4], o[5], acc[i][2]);
            UNPACK2(o[6], o[7], acc[i][3]);
            float* dst = Cmat + (size_t)(bm + ty * 8 + i) * GATES + bn * 128 + tx * 8;
            *reinterpret_cast<float4*>(dst)     = make_float4(o[0], o[1], o[2], o[3]);
            *reinterpret_cast<float4*>(dst + 4) = make_float4(o[4], o[5], o[6], o[7]);
        }
    }
}

// ---------------------------------------------------------------------------
// Serial instruction LSTM — R1 skeleton (barrier.cluster, proven ~2400cyc)
// with: f32x2 dot (256-cyc floor), fast MUFU gates, precomputed mapa bases,
// projection off the barrier path.
// ---------------------------------------------------------------------------
__global__ void __launch_bounds__(512, 1) __cluster_dims__(NCLUS, 1, 1)
ins_lstm(const float* __restrict__ G,
         const float* __restrict__ Whh,
         const float* __restrict__ bih,
         const float* __restrict__ bhh,
         const float* __restrict__ Wl,
         float* __restrict__ part)
{
    // h buffers: 4 chunks of 64 floats, padded to 68 (conflict-free f32x2 LDS)
    __shared__ __align__(16) float hbuf[2][4 * 68];
    __shared__ float gs[128];
    __shared__ float hn[32];

    const int tid = threadIdx.x;
    const int cta = blockIdx.x;
    const int r   = tid >> 2;            // gate row within CTA, 0..127
    const int q   = tid & 3;             // 64-wide k chunk
    const int grow = (r >> 5) * 256 + cta * 32 + (r & 31);

    // pack this thread's 64 weights as 32 f32x2 pairs
    unsigned long long w2[32];
#pragma unroll
    for (int jj = 0; jj < 16; ++jj) {
        const float4 v = *reinterpret_cast<const float4*>(
            Whh + (size_t)grow * 256 + q * 64 + jj * 4);
        asm("mov.b64 %0, {%1, %2};" : "=l"(w2[2 * jj])
            : "r"(__float_as_uint(v.x)), "r"(__float_as_uint(v.y)));
        asm("mov.b64 %0, {%1, %2};" : "=l"(w2[2 * jj + 1])
            : "r"(__float_as_uint(v.z)), "r"(__float_as_uint(v.w)));
    }
    const float brow = bih[grow] + bhh[grow];
    const float wl = (tid < 32) ? Wl[cta * 32 + tid] : 0.0f;
    float cst = 0.0f;

    for (int i = tid; i < 2 * 4 * 68; i += 512)
        (&hbuf[0][0])[i] = 0.0f;

    // precompute this thread's peer broadcast address base (threads 0..255)
    const uint32_t hbase = (uint32_t)__cvta_generic_to_shared(&hbuf[0][0]);
    uint32_t rbase = 0;
    {
        const int peer = (tid >> 5) & 7;
        asm("mapa.shared::cluster.u32 %0, %1, %2;"
            : "=r"(rbase) : "r"(hbase), "r"(peer));
        const int el = tid & 31;
        const int vg = cta * 32 + el;                 // global h index
        const int di = (vg >> 6) * 68 + (vg & 63);    // padded layout
        rbase += (uint32_t)(di * 4);
    }

    __syncthreads();
    asm volatile("barrier.cluster.arrive.aligned;" ::: "memory");
    asm volatile("barrier.cluster.wait.aligned;" ::: "memory");

    float gp0 = 0.0f, gp1 = 0.0f;
    if (q == 0) {
        gp0 = __ldg(&G[grow]);
        gp1 = __ldg(&G[GATES + grow]);
    }

    int p = 0;
    for (int s = 0; s < N_INS; ++s) {
        // prefetch x-part of gates 2 steps ahead
        float gn = 0.0f;
        if (q == 0) {
            const int sn = (s + 2 < N_INS) ? s + 2 : N_INS - 1;
            gn = __ldg(&G[(size_t)sn * GATES + grow]);
        }

        // packed dot over this thread's 64-chunk of h
        const ulonglong2* hp = reinterpret_cast<const ulonglong2*>(&hbuf[p][q * 68]);
        unsigned long long a2 = 0ULL, b2 = 0ULL;
#pragma unroll
        for (int jj = 0; jj < 16; ++jj) {
            const ulonglong2 hv = hp[jj];
            FMA2(a2, w2[2 * jj],     hv.x);
            FMA2(b2, w2[2 * jj + 1], hv.y);
        }
        float s0, s1, s2, s3;
        UNPACK2(s0, s1, a2);
        UNPACK2(s2, s3, b2);
        float acc = (s0 + s1) + (s2 + s3);
        acc += __shfl_xor_sync(0xffffffffu, acc, 1);
        acc += __shfl_xor_sync(0xffffffffu, acc, 2);
        if (q == 0) gs[r] = acc + gp0 + brow;
        gp0 = gp1; gp1 = gn;
        __syncthreads();                       // (1) gs ready

        if (tid < 32) {
            const float gi = gs[tid];
            const float gf = gs[32 + tid];
            const float gg = gs[64 + tid];
            const float go = gs[96 + tid];
            cst = fsig(gf) * cst + fsig(gi) * ftanh_(gg);
            const float h = fsig(go) * ftanh_(cst);
            hn[tid] = h;

            // output projection (off the barrier path)
            float pp = h * wl;
#pragma unroll
            for (int o = 16; o > 0; o >>= 1)
                pp += __shfl_xor_sync(0xffffffffu, pp, o);
            if (tid == 0) part[(size_t)cta * N_INS + s] = pp;
        }
        __syncthreads();                       // (2) hn ready

        // broadcast: threads 0..255, thread -> (peer = tid>>5, el = tid&31)
        if (tid < 256) {
            const float v = hn[tid & 31];
            const uint32_t dst = rbase + (uint32_t)((p ^ 1) * 4 * 68 * 4);
            asm volatile("st.shared::cluster.b32 [%0], %1;"
                         :: "r"(dst), "r"(__float_as_uint(v)) : "memory");
        }

        asm volatile("barrier.cluster.arrive.aligned;" ::: "memory");
        asm volatile("barrier.cluster.wait.aligned;" ::: "memory");
        p ^= 1;
    }
}

// ---------------------------------------------------------------------------
__global__ void __launch_bounds__(256)
finalize(float* __restrict__ out, const float* __restrict__ part,
         const float* __restrict__ bl)
{
    const int n = blockIdx.x * 256 + threadIdx.x;
    float s = bl[0];
#pragma unroll
    for (int k = 0; k < NCLUS; ++k) s += part[(size_t)k * N_INS + n];
    out[n] = s;
}

// ---------------------------------------------------------------------------
extern "C" void kernel_launch(void* const* d_in, const int* in_sizes, int n_in,
                              void* d_out, int out_size)
{
    const float* tokens = (const float*)d_in[0];
    const int*   lengths= (const int*)  d_in[1];
    const float* Wih_t  = (const float*)d_in[2];
    const float* Whh_t  = (const float*)d_in[3];
    const float* bih_t  = (const float*)d_in[4];
    const float* bhh_t  = (const float*)d_in[5];
    const float* Wih_i  = (const float*)d_in[6];
    const float* Whh_i  = (const float*)d_in[7];
    const float* bih_i  = (const float*)d_in[8];
    const float* bhh_i  = (const float*)d_in[9];
    const float* Wl     = (const float*)d_in[10];
    const float* bl     = (const float*)d_in[11];
    float* out = (float*)d_out;

    float *H, *C, *G, *part;
    cudaGetSymbolAddress((void**)&H,    g_H);
    cudaGetSymbolAddress((void**)&C,    g_C);
    cudaGetSymbolAddress((void**)&G,    g_G);
    cudaGetSymbolAddress((void**)&part, g_part);

    cudaMemsetAsync(H, 0, (size_t)2 * N_INS * HID * sizeof(float));
    cudaMemsetAsync(C, 0, (size_t)N_INS * HID * sizeof(float));

    const size_t NH = (size_t)N_INS * HID;
    dim3 grid(N_INS / 128, 8);

    // ---- token-level LSTM: 16 fused GEMM+pointwise steps (H ping-pong) ----
    for (int t = 0; t < T_MAX; ++t) {
        float* hr = H + (size_t)(t & 1) * NH;
        float* hw = H + (size_t)((t & 1) ^ 1) * NH;
        gemm_k<1><<<grid, 256>>>(nullptr,
                                 tokens + (size_t)t * HID, T_MAX * HID, Wih_t,
                                 hr, Whh_t,
                                 lengths, bih_t, bhh_t,
                                 hr, hw, C, t);
    }

    // ---- precompute ins_embeds @ Wih_i^T into G ----
    gemm_k<0><<<grid, 256>>>(G, H, HID, Wih_i,
                             nullptr, nullptr, nullptr, nullptr, nullptr,
                             nullptr, nullptr, nullptr, 0);

    // ---- serial instruction-level LSTM (8-CTA cluster, barrier.cluster) ----
    ins_lstm<<<NCLUS, 512>>>(G, Whh_i, bih_i, bhh_i, Wl, part);

    // ---- output projection finalize ----
    finalize<<<N_INS / 256, 256>>>(out, part, bl);
}

// round 5
// speedup vs baseline: 2.4643x; 1.2569x over previous
#include <cuda_runtime.h>
#include <cstdint>

#define N_INS 8192
#define T_MAX 16
#define HID   256
#define GATES 1024
#define NCLUS 8

// ---------------- scratch (static device globals; no allocations) ----------
__device__ float g_H[2 * N_INS * HID];    // ping-pong hidden state
__device__ float g_C[N_INS * HID];        // cell state
__device__ float g_G[N_INS * GATES];      // precomputed ins_embeds @ Wih_i^T
__device__ float g_part[NCLUS * N_INS];   // per-cluster-CTA output partials

// ---------------- packed f32x2 helpers ----------
#define FMA2(d, a, b) \
    asm("fma.rn.f32x2 %0, %1, %2, %0;" : "+l"(d) : "l"(a), "l"(b))
#define UNPACK2(lo, hi, v) \
    asm("mov.b64 {%0, %1}, %2;" : "=f"(lo), "=f"(hi) : "l"(v))

__device__ __forceinline__ float fsig(float x) {
    return __fdividef(1.0f, 1.0f + __expf(-x));
}
__device__ __forceinline__ float ftanh_(float x) {
    float e2 = __expf(2.0f * fminf(x, 30.0f));
    return __fdividef(e2 - 1.0f, e2 + 1.0f);
}

__device__ __forceinline__ void fma8(unsigned long long* acc, float a,
                                     const ulonglong2& w01, const ulonglong2& w23) {
    unsigned long long ap;
    asm("mov.b64 %0, {%1, %1};" : "=l"(ap) : "r"(__float_as_uint(a)));
    FMA2(acc[0], ap, w01.x);
    FMA2(acc[1], ap, w01.y);
    FMA2(acc[2], ap, w23.x);
    FMA2(acc[3], ap, w23.y);
}

// ---------------------------------------------------------------------------
// f32x2 GEMM, 128x128 tile, 256 threads, 8x8 micro-tile (measured 216us).
// MODE 1: dual-source + fused token-LSTM epilogue (gate-interleaved cols).
// MODE 0: single source, plain C = A1 @ W1^T.
// ---------------------------------------------------------------------------
template<int MODE>
__global__ void __launch_bounds__(256)
gemm_k(float* __restrict__ Cmat,
       const float* __restrict__ A1, int lda1, const float* __restrict__ W1,
       const float* __restrict__ A2, const float* __restrict__ W2,
       const int* __restrict__ lengths,
       const float* __restrict__ bih, const float* __restrict__ bhh,
       const float* __restrict__ Hr, float* __restrict__ Hw,
       float* __restrict__ Cs, int t)
{
    __shared__ __align__(16) float As[16][132];
    __shared__ __align__(16) float Ws[16][132];

    const int tid = threadIdx.x;
    const int bm  = blockIdx.x * 128;
    const int bn  = blockIdx.y;
    const int tx  = tid & 15;
    const int ty  = tid >> 4;
    const int NT  = (MODE == 1) ? 32 : 16;

    const int lrow = tid >> 2;
    const int kq   = (tid & 3) << 2;

    int wr0, wr1;
    if (MODE == 1) {
        wr0 = (lrow & 3) * 256 + bn * 32 + (lrow >> 2);
        const int c1 = lrow + 64;
        wr1 = (c1 & 3) * 256 + bn * 32 + (c1 >> 2);
    } else {
        wr0 = bn * 128 + lrow;
        wr1 = bn * 128 + lrow + 64;
    }

    unsigned long long acc[8][4];
#pragma unroll
    for (int i = 0; i < 8; ++i)
#pragma unroll
        for (int j = 0; j < 4; ++j) acc[i][j] = 0ULL;

    float4 pa0, pa1, pw0, pw1;
    pa0 = *reinterpret_cast<const float4*>(A1 + (size_t)(bm + lrow)      * lda1 + kq);
    pa1 = *reinterpret_cast<const float4*>(A1 + (size_t)(bm + lrow + 64) * lda1 + kq);
    pw0 = *reinterpret_cast<const float4*>(W1 + (size_t)wr0 * 256 + kq);
    pw1 = *reinterpret_cast<const float4*>(W1 + (size_t)wr1 * 256 + kq);

    for (int tt = 0; tt < NT; ++tt) {
        __syncthreads();
        As[kq + 0][lrow] = pa0.x; As[kq + 1][lrow] = pa0.y;
        As[kq + 2][lrow] = pa0.z; As[kq + 3][lrow] = pa0.w;
        As[kq + 0][lrow + 64] = pa1.x; As[kq + 1][lrow + 64] = pa1.y;
        As[kq + 2][lrow + 64] = pa1.z; As[kq + 3][lrow + 64] = pa1.w;
        Ws[kq + 0][lrow] = pw0.x; Ws[kq + 1][lrow] = pw0.y;
        Ws[kq + 2][lrow] = pw0.z; Ws[kq + 3][lrow] = pw0.w;
        Ws[kq + 0][lrow + 64] = pw1.x; Ws[kq + 1][lrow + 64] = pw1.y;
        Ws[kq + 2][lrow + 64] = pw1.z; Ws[kq + 3][lrow + 64] = pw1.w;
        __syncthreads();

        if (tt + 1 < NT) {
            const int ts = tt + 1;
            const float* A; const float* W; int lda, k0;
            if (MODE == 1 && ts >= 16) { A = A2; lda = 256; W = W2; k0 = (ts - 16) * 16; }
            else                       { A = A1; lda = lda1; W = W1; k0 = ts * 16; }
            pa0 = *reinterpret_cast<const float4*>(A + (size_t)(bm + lrow)      * lda + k0 + kq);
            pa1 = *reinterpret_cast<const float4*>(A + (size_t)(bm + lrow + 64) * lda + k0 + kq);
            pw0 = *reinterpret_cast<const float4*>(W + (size_t)wr0 * 256 + k0 + kq);
            pw1 = *reinterpret_cast<const float4*>(W + (size_t)wr1 * 256 + k0 + kq);
        }

#pragma unroll
        for (int k = 0; k < 16; ++k) {
            const float4 a0 = *reinterpret_cast<const float4*>(&As[k][ty * 8]);
            const float4 a1 = *reinterpret_cast<const float4*>(&As[k][ty * 8 + 4]);
            const ulonglong2 w01 = *reinterpret_cast<const ulonglong2*>(&Ws[k][tx * 8]);
            const ulonglong2 w23 = *reinterpret_cast<const ulonglong2*>(&Ws[k][tx * 8 + 4]);
            fma8(acc[0], a0.x, w01, w23);
            fma8(acc[1], a0.y, w01, w23);
            fma8(acc[2], a0.z, w01, w23);
            fma8(acc[3], a0.w, w01, w23);
            fma8(acc[4], a1.x, w01, w23);
            fma8(acc[5], a1.y, w01, w23);
            fma8(acc[6], a1.z, w01, w23);
            fma8(acc[7], a1.w, w01, w23);
        }
    }

    if (MODE == 1) {
        const int ebase = bn * 32 + tx * 2;
        float b0[2], b1[2], b2[2], b3[2];
#pragma unroll
        for (int ee = 0; ee < 2; ++ee) {
            b0[ee] = bih[      ebase + ee] + bhh[      ebase + ee];
            b1[ee] = bih[256 + ebase + ee] + bhh[256 + ebase + ee];
            b2[ee] = bih[512 + ebase + ee] + bhh[512 + ebase + ee];
            b3[ee] = bih[768 + ebase + ee] + bhh[768 + ebase + ee];
        }
#pragma unroll
        for (int i = 0; i < 8; ++i) {
            const int m = bm + ty * 8 + i;
            const bool act = (t < lengths[m]);
#pragma unroll
            for (int ee = 0; ee < 2; ++ee) {
                const int off = m * 256 + ebase + ee;
                if (act) {
                    float gi, gf, gg, go;
                    UNPACK2(gi, gf, acc[i][ee * 2]);
                    UNPACK2(gg, go, acc[i][ee * 2 + 1]);
                    gi += b0[ee]; gf += b1[ee]; gg += b2[ee]; go += b3[ee];
                    float c = Cs[off];
                    c = fsig(gf) * c + fsig(gi) * ftanh_(gg);
                    Cs[off] = c;
                    Hw[off] = fsig(go) * ftanh_(c);
                } else {
                    Hw[off] = Hr[off];
                }
            }
        }
    } else {
#pragma unroll
        for (int i = 0; i < 8; ++i) {
            float o[8];
            UNPACK2(o[0], o[1], acc[i][0]);
            UNPACK2(o[2], o[3], acc[i][1]);
            UNPACK2(o[4], o[5], acc[i][2]);
            UNPACK2(o[6], o[7], acc[i][3]);
            float* dst = Cmat + (size_t)(bm + ty * 8 + i) * GATES + bn * 128 + tx * 8;
            *reinterpret_cast<float4*>(dst)     = make_float4(o[0], o[1], o[2], o[3]);
            *reinterpret_cast<float4*>(dst + 4) = make_float4(o[4], o[5], o[6], o[7]);
        }
    }
}

// ---------------------------------------------------------------------------
// Serial instruction LSTM: 8-CTA cluster. Per-step sync via st.async
// (remote data store fused with remote mbarrier complete_tx) + cheap LOCAL
// mbarrier.try_wait.parity.acquire.cta. No barrier.cluster in the loop.
// hbuf layout: 4 chunks of 64 floats padded to 68 (conflict-free f32x2 LDS);
// h element vg lives at float index (vg>>6)*68 + (vg&63).
// ---------------------------------------------------------------------------
__global__ void __launch_bounds__(512, 1) __cluster_dims__(NCLUS, 1, 1)
ins_lstm(const float* __restrict__ G,
         const float* __restrict__ Whh,
         const float* __restrict__ bih,
         const float* __restrict__ bhh,
         const float* __restrict__ Wl,
         float* __restrict__ part)
{
    __shared__ __align__(16) float hbuf[2][272];   // 2 x (4*68)
    __shared__ float gs[128];
    __shared__ __align__(16) unsigned long long bar2[2];

    const int tid = threadIdx.x;
    const int cta = blockIdx.x;
    const int r   = tid >> 2;            // gate row within CTA, 0..127
    const int q   = tid & 3;             // 64-wide k chunk
    const int grow = (r >> 5) * 256 + cta * 32 + (r & 31);

    // pack this thread's 64 weights as 32 f32x2 pairs
    unsigned long long w2[32];
#pragma unroll
    for (int jj = 0; jj < 16; ++jj) {
        const float4 v = *reinterpret_cast<const float4*>(
            Whh + (size_t)grow * 256 + q * 64 + jj * 4);
        asm("mov.b64 %0, {%1, %2};" : "=l"(w2[2 * jj])
            : "r"(__float_as_uint(v.x)), "r"(__float_as_uint(v.y)));
        asm("mov.b64 %0, {%1, %2};" : "=l"(w2[2 * jj + 1])
            : "r"(__float_as_uint(v.z)), "r"(__float_as_uint(v.w)));
    }
    const float brow = bih[grow] + bhh[grow];
    const float wl = (tid < 32) ? Wl[cta * 32 + tid] : 0.0f;
    float cst = 0.0f;

    for (int i = tid; i < 2 * 272; i += 512)
        (&hbuf[0][0])[i] = 0.0f;

    const uint32_t hbase = (uint32_t)__cvta_generic_to_shared(&hbuf[0][0]);
    const uint32_t bbase = (uint32_t)__cvta_generic_to_shared(&bar2[0]);

    // init + pre-arm both barriers (count=1; expect 8 CTAs * 128B = 1024B)
    if (tid == 0) {
        asm volatile("mbarrier.init.shared.b64 [%0], 1;" :: "r"(bbase) : "memory");
        asm volatile("mbarrier.init.shared.b64 [%0], 1;" :: "r"(bbase + 8) : "memory");
        asm volatile("mbarrier.arrive.expect_tx.shared.b64 _, [%0], 1024;"
                     :: "r"(bbase) : "memory");
        asm volatile("mbarrier.arrive.expect_tx.shared.b64 _, [%0], 1024;"
                     :: "r"(bbase + 8) : "memory");
    }

    // per-lane remote addresses (used by warp0 lanes 0..15): for peer j,
    // data dst = peer hbuf + chunk offset of this CTA's 32 h values + lane*8
    uint32_t rh[NCLUS];   // remote hbuf (buffer 0) + byte offset for this lane
    uint32_t rb[NCLUS];   // remote bar2 base
    {
        const uint32_t coff = (uint32_t)(((cta >> 1) * 68 + (cta & 1) * 32) * 4
                                         + (tid & 15) * 8);
#pragma unroll
        for (int j = 0; j < NCLUS; ++j) {
            uint32_t a, b;
            asm("mapa.shared::cluster.u32 %0, %1, %2;" : "=r"(a) : "r"(hbase), "r"(j));
            asm("mapa.shared::cluster.u32 %0, %1, %2;" : "=r"(b) : "r"(bbase), "r"(j));
            rh[j] = a + coff;
            rb[j] = b;
        }
    }

    __syncthreads();
    asm volatile("barrier.cluster.arrive.aligned;" ::: "memory");
    asm volatile("barrier.cluster.wait.aligned;" ::: "memory");

    float gp0 = 0.0f, gp1 = 0.0f;
    if (q == 0) {
        gp0 = __ldg(&G[grow]);
        gp1 = __ldg(&G[GATES + grow]);
    }

    int php0 = 0, php1 = 0;   // parity trackers for bar2[0], bar2[1]
    for (int s = 0; s < N_INS; ++s) {
        const int p = s & 1;

        if (s > 0) {
            // wait for this step's h (local, cheap) + re-arm for step s+2
            const uint32_t ba = bbase + (uint32_t)(p * 8);
            const int ph = p ? php1 : php0;
            asm volatile(
                "{\n\t.reg .pred P;\n"
                "WL%=:\n\t"
                "mbarrier.try_wait.parity.acquire.cta.shared::cta.b64 P, [%0], %1, 0x989680;\n\t"
                "@!P bra WL%=;\n\t}"
                :: "r"(ba), "r"(ph) : "memory");
            if (p) php1 ^= 1; else php0 ^= 1;
            if (tid == 0)
                asm volatile("mbarrier.arrive.expect_tx.shared.b64 _, [%0], 1024;"
                             :: "r"(ba) : "memory");
        }

        // prefetch x-part of gates 2 steps ahead
        float gn = 0.0f;
        if (q == 0) {
            const int sn = (s + 2 < N_INS) ? s + 2 : N_INS - 1;
            gn = __ldg(&G[(size_t)sn * GATES + grow]);
        }

        // packed dot over this thread's 64-chunk of h
        const ulonglong2* hp = reinterpret_cast<const ulonglong2*>(&hbuf[p][q * 68]);
        unsigned long long a2 = 0ULL, b2 = 0ULL;
#pragma unroll
        for (int jj = 0; jj < 16; ++jj) {
            const ulonglong2 hv = hp[jj];
            FMA2(a2, w2[2 * jj],     hv.x);
            FMA2(b2, w2[2 * jj + 1], hv.y);
        }
        float s0, s1, s2, s3;
        UNPACK2(s0, s1, a2);
        UNPACK2(s2, s3, b2);
        float acc = (s0 + s1) + (s2 + s3);
        acc += __shfl_xor_sync(0xffffffffu, acc, 1);
        acc += __shfl_xor_sync(0xffffffffu, acc, 2);
        if (q == 0) gs[r] = acc + gp0 + brow;
        gp0 = gp1; gp1 = gn;
        __syncthreads();                       // gs ready (and all hbuf[p] reads done)

        if (tid < 32) {
            const float gi = gs[tid];
            const float gf = gs[32 + tid];
            const float gg = gs[64 + tid];
            const float go = gs[96 + tid];
            cst = fsig(gf) * cst + fsig(gi) * ftanh_(gg);
            const float h = fsig(go) * ftanh_(cst);

            // pack pairs on lanes 0..15 and st.async to all 8 peers
            const float hlo = __shfl_sync(0xffffffffu, h, (tid & 15) * 2);
            const float hhi = __shfl_sync(0xffffffffu, h, (tid & 15) * 2 + 1);
            if (tid < 16 && s + 1 < N_INS) {
                unsigned long long pkt;
                asm("mov.b64 %0, {%1, %2};" : "=l"(pkt)
                    : "r"(__float_as_uint(hlo)), "r"(__float_as_uint(hhi)));
                const uint32_t bufo = (uint32_t)((p ^ 1) * 272 * 4);
                const uint32_t baro = (uint32_t)((p ^ 1) * 8);
#pragma unroll
                for (int j = 0; j < NCLUS; ++j) {
                    asm volatile(
                        "st.async.shared::cluster.mbarrier::complete_tx::bytes.b64 "
                        "[%0], %1, [%2];"
                        :: "r"(rh[j] + bufo), "l"(pkt), "r"(rb[j] + baro)
                        : "memory");
                }
            }

            // output projection (off the sync path)
            float pp = h * wl;
#pragma unroll
            for (int o = 16; o > 0; o >>= 1)
                pp += __shfl_xor_sync(0xffffffffu, pp, o);
            if (tid == 0) part[(size_t)cta * N_INS + s] = pp;
        }
    }
    // last step sends nothing; the step-8191 wait already drained all traffic.
}

// ---------------------------------------------------------------------------
__global__ void __launch_bounds__(256)
finalize(float* __restrict__ out, const float* __restrict__ part,
         const float* __restrict__ bl)
{
    const int n = blockIdx.x * 256 + threadIdx.x;
    float s = bl[0];
#pragma unroll
    for (int k = 0; k < NCLUS; ++k) s += part[(size_t)k * N_INS + n];
    out[n] = s;
}

// ---------------------------------------------------------------------------
extern "C" void kernel_launch(void* const* d_in, const int* in_sizes, int n_in,
                              void* d_out, int out_size)
{
    const float* tokens = (const float*)d_in[0];
    const int*   lengths= (const int*)  d_in[1];
    const float* Wih_t  = (const float*)d_in[2];
    const float* Whh_t  = (const float*)d_in[3];
    const float* bih_t  = (const float*)d_in[4];
    const float* bhh_t  = (const float*)d_in[5];
    const float* Wih_i  = (const float*)d_in[6];
    const float* Whh_i  = (const float*)d_in[7];
    const float* bih_i  = (const float*)d_in[8];
    const float* bhh_i  = (const float*)d_in[9];
    const float* Wl     = (const float*)d_in[10];
    const float* bl     = (const float*)d_in[11];
    float* out = (float*)d_out;

    float *H, *C, *G, *part;
    cudaGetSymbolAddress((void**)&H,    g_H);
    cudaGetSymbolAddress((void**)&C,    g_C);
    cudaGetSymbolAddress((void**)&G,    g_G);
    cudaGetSymbolAddress((void**)&part, g_part);

    cudaMemsetAsync(H, 0, (size_t)2 * N_INS * HID * sizeof(float));
    cudaMemsetAsync(C, 0, (size_t)N_INS * HID * sizeof(float));

    const size_t NH = (size_t)N_INS * HID;
    dim3 grid(N_INS / 128, 8);

    // ---- token-level LSTM: 16 fused GEMM+pointwise steps (H ping-pong) ----
    for (int t = 0; t < T_MAX; ++t) {
        float* hr = H + (size_t)(t & 1) * NH;
        float* hw = H + (size_t)((t & 1) ^ 1) * NH;
        gemm_k<1><<<grid, 256>>>(nullptr,
                                 tokens + (size_t)t * HID, T_MAX * HID, Wih_t,
                                 hr, Whh_t,
                                 lengths, bih_t, bhh_t,
                                 hr, hw, C, t);
    }

    // ---- precompute ins_embeds @ Wih_i^T into G ----
    gemm_k<0><<<grid, 256>>>(G, H, HID, Wih_i,
                             nullptr, nullptr, nullptr, nullptr, nullptr,
                             nullptr, nullptr, nullptr, 0);

    // ---- serial instruction-level LSTM (8-CTA cluster, st.async sync) ----
    ins_lstm<<<NCLUS, 512>>>(G, Whh_i, bih_i, bhh_i, Wl, part);

    // ---- output projection finalize ----
    finalize<<<N_INS / 256, 256>>>(out, part, bl);
}